// round 4
// baseline (speedup 1.0000x reference)
#include <cuda_runtime.h>
#include <cuda_bf16.h>
#include <math.h>

typedef unsigned int uint;

#define BB 2
#define SEQ 2048
#define EMB 1024
#define NH 16
#define DH 64
#define MTOT (BB * SEQ)          // 4096

// 0.125 * log2(e): fold softmax scale + exp->exp2 conversion into Q
#define QSCALE 0.18033688011112042f

// ---------------- bf16 hi/lo scratch planes ----------------
__device__ __nv_bfloat16 g_dech[MTOT * EMB], g_decl[MTOT * EMB];
__device__ __nv_bfloat16 g_ench[MTOT * EMB], g_encl[MTOT * EMB];
__device__ __nv_bfloat16 g_wqh[NH * EMB * DH], g_wql[NH * EMB * DH];
__device__ __nv_bfloat16 g_wkh[NH * EMB * DH], g_wkl[NH * EMB * DH];
__device__ __nv_bfloat16 g_wvh[NH * EMB * DH], g_wvl[NH * EMB * DH];
__device__ __nv_bfloat16 g_woh[EMB * EMB],    g_wol[EMB * EMB];
__device__ __nv_bfloat16 g_Qh[BB * NH * SEQ * DH], g_Ql[BB * NH * SEQ * DH];
__device__ __nv_bfloat16 g_Kh[BB * NH * SEQ * DH], g_Kl[BB * NH * SEQ * DH];
__device__ __nv_bfloat16 g_Vth[BB * NH * DH * SEQ], g_Vtl[BB * NH * DH * SEQ]; // [bh][d][key]
__device__ __nv_bfloat16 g_ctxh[MTOT * EMB], g_ctxl[MTOT * EMB];

// ---------------- helpers ----------------
__device__ __forceinline__ uint pack_bf16x2(float lo_elem, float hi_elem) {
    uint r;
    asm("cvt.rn.bf16x2.f32 %0, %1, %2;" : "=r"(r) : "f"(hi_elem), "f"(lo_elem));
    return r;
}
__device__ __forceinline__ void split_pair(float x0, float x1, uint& h, uint& l) {
    h = pack_bf16x2(x0, x1);
    float h0 = __uint_as_float(h << 16);
    float h1 = __uint_as_float(h & 0xffff0000u);
    l = pack_bf16x2(x0 - h0, x1 - h1);
}
__device__ __forceinline__ void split_scalar(float x, __nv_bfloat16& h, __nv_bfloat16& l) {
    h = __float2bfloat16_rn(x);
    l = __float2bfloat16_rn(x - __bfloat162float(h));
}
__device__ __forceinline__ float fast_ex2(float x) {
    float y; asm("ex2.approx.f32 %0, %1;" : "=f"(y) : "f"(x)); return y;
}

#define MMA_BF16(d, a0, a1, a2, a3, b0, b1)                                    \
    asm volatile(                                                              \
        "mma.sync.aligned.m16n8k16.row.col.f32.bf16.bf16.f32 "                 \
        "{%0,%1,%2,%3}, {%4,%5,%6,%7}, {%8,%9}, {%0,%1,%2,%3};"                \
        : "+f"(d[0]), "+f"(d[1]), "+f"(d[2]), "+f"(d[3])                       \
        : "r"(a0), "r"(a1), "r"(a2), "r"(a3), "r"(b0), "r"(b1))

#define LDSM4(r0, r1, r2, r3, addr)                                            \
    asm volatile("ldmatrix.sync.aligned.m8n8.x4.shared.b16 {%0,%1,%2,%3}, [%4];" \
        : "=r"(r0), "=r"(r1), "=r"(r2), "=r"(r3) : "r"(addr))

__device__ __forceinline__ uint ldsw(const __nv_bfloat16* p) { return *(const uint*)p; }

__device__ __forceinline__ void cp_async16(uint saddr, const void* gptr) {
    asm volatile("cp.async.cg.shared.global [%0], [%1], 16;" :: "r"(saddr), "l"(gptr));
}
#define CP_COMMIT() asm volatile("cp.async.commit_group;")
#define CP_WAIT1()  asm volatile("cp.async.wait_group 1;")

// ---------------- fused split kernels: fp32 -> bf16 hi/lo ----------------
__device__ __forceinline__ void split_body(const float* __restrict__ x,
    __nv_bfloat16* __restrict__ h, __nv_bfloat16* __restrict__ l, int n)
{
    int i = (blockIdx.x * 256 + threadIdx.x) * 2;
    if (i < n) {
        float2 v = *(const float2*)(x + i);
        uint hh, ll;
        split_pair(v.x, v.y, hh, ll);
        *(uint*)(h + i) = hh;
        *(uint*)(l + i) = ll;
    }
}

__global__ void __launch_bounds__(256) split_duo(
    const float* __restrict__ x0, __nv_bfloat16* h0, __nv_bfloat16* l0,
    const float* __restrict__ x1, __nv_bfloat16* h1, __nv_bfloat16* l1, int n)
{
    if (blockIdx.y == 0) split_body(x0, h0, l0, n);
    else                 split_body(x1, h1, l1, n);
}

__global__ void __launch_bounds__(256) split_quad(
    const float* __restrict__ x0, __nv_bfloat16* h0, __nv_bfloat16* l0,
    const float* __restrict__ x1, __nv_bfloat16* h1, __nv_bfloat16* l1,
    const float* __restrict__ x2, __nv_bfloat16* h2, __nv_bfloat16* l2,
    const float* __restrict__ x3, __nv_bfloat16* h3, __nv_bfloat16* l3, int n)
{
    switch (blockIdx.y) {
        case 0: split_body(x0, h0, l0, n); break;
        case 1: split_body(x1, h1, l1, n); break;
        case 2: split_body(x2, h2, l2, n); break;
        default: split_body(x3, h3, l3, n); break;
    }
}

// ---------------------------------------------------------------------------
// GEMM via mma.sync bf16 split-3, ldmatrix fragment loads.
// ---------------------------------------------------------------------------
#define SA 40
#define A_PL (128 * SA)          // elems per A plane
#define W_OFF (2 * A_PL)         // sWh start
#define W_PL (64 * SA)

template <int MODE, bool SCALE, bool TRANSV>
__global__ void __launch_bounds__(256) gemm_mma(
    const __nv_bfloat16* __restrict__ Ah, const __nv_bfloat16* __restrict__ Al,
    const __nv_bfloat16* __restrict__ Wh, const __nv_bfloat16* __restrict__ Wl,
    const float* __restrict__ bias,
    __nv_bfloat16* __restrict__ Oh, __nv_bfloat16* __restrict__ Ol,
    float* __restrict__ Of)
{
    __shared__ __nv_bfloat16 smg[2 * A_PL + 2 * W_PL];
    __nv_bfloat16* sAh = smg;
    __nv_bfloat16* sAl = smg + A_PL;
    __nv_bfloat16* sWh = smg + W_OFF;
    __nv_bfloat16* sWl = sWh + W_PL;

    const int n0 = blockIdx.x * 64;
    const int m0 = blockIdx.y * 128;
    const int tid = threadIdx.x;
    const int lane = tid & 31, wid = tid >> 5;
    const int wm = wid & 3, wn = wid >> 2;
    const int g = lane >> 2, tig = lane & 3;

    // ldmatrix lane-static byte offsets
    const uint smg_u32 = (uint)__cvta_generic_to_shared(smg);
    // A: matrices (rowblk, colblk): lanes 0-7 rows r.., 8-15 rows r+8, 16-23 cols+8, 24-31 rows+8 cols+8
    const uint a_stat = smg_u32
        + (uint)((((lane >> 3) & 1) * 8 + (lane & 7)) * SA * 2)
        + (uint)((lane >> 4) * 16);
    // B/W: lanes 0-7 hi cols cb, 8-15 hi cols cb+8, 16-31 lo same
    const uint w_stat = smg_u32 + (uint)(W_OFF * 2)
        + (uint)((lane & 7) * SA * 2)
        + (uint)(((lane >> 3) & 1) * 16)
        + (uint)((lane >> 4) * (W_PL * 2));

    float acc[2][4][4] = {};

    const int arow = tid & 127, acb = (tid >> 7) * 16;
    const int wnn = tid & 63,  wkb = (tid >> 6) * 8;

    for (int k0 = 0; k0 < EMB; k0 += 32) {
        {
            const __nv_bfloat16* s = Ah + (size_t)(m0 + arow) * EMB + k0 + acb;
            uint4 v0 = *(const uint4*)s, v1 = *(const uint4*)(s + 8);
            *(uint4*)(sAh + arow * SA + acb) = v0;
            *(uint4*)(sAh + arow * SA + acb + 8) = v1;
            s = Al + (size_t)(m0 + arow) * EMB + k0 + acb;
            v0 = *(const uint4*)s; v1 = *(const uint4*)(s + 8);
            *(uint4*)(sAl + arow * SA + acb) = v0;
            *(uint4*)(sAl + arow * SA + acb + 8) = v1;
        }
#pragma unroll
        for (int kk = 0; kk < 8; kk++) {
            size_t widx;
            if (MODE == 0)
                widx = ((size_t)blockIdx.x * EMB + (k0 + wkb + kk)) * DH + wnn;
            else
                widx = (size_t)(k0 + wkb + kk) * EMB + n0 + wnn;
            sWh[wnn * SA + wkb + kk] = Wh[widx];
            sWl[wnn * SA + wkb + kk] = Wl[widx];
        }
        __syncthreads();

#pragma unroll
        for (int ks = 0; ks < 2; ks++) {
            uint ah[2][4], al2[2][4];
#pragma unroll
            for (int i = 0; i < 2; i++) {
                const uint ab = a_stat + (uint)((wm * 32 + 16 * i) * SA * 2 + ks * 32);
                LDSM4(ah[i][0], ah[i][1], ah[i][2], ah[i][3], ab);
                LDSM4(al2[i][0], al2[i][1], al2[i][2], al2[i][3], ab + A_PL * 2);
            }
#pragma unroll
            for (int j = 0; j < 4; j++) {
                uint bh0, bh1, bl0, bl1;
                LDSM4(bh0, bh1, bl0, bl1,
                      w_stat + (uint)((wn * 32 + 8 * j) * SA * 2 + ks * 32));
#pragma unroll
                for (int i = 0; i < 2; i++) {
                    MMA_BF16(acc[i][j], ah[i][0], ah[i][1], ah[i][2], ah[i][3], bh0, bh1);
                    MMA_BF16(acc[i][j], ah[i][0], ah[i][1], ah[i][2], ah[i][3], bl0, bl1);
                    MMA_BF16(acc[i][j], al2[i][0], al2[i][1], al2[i][2], al2[i][3], bh0, bh1);
                }
            }
        }
        __syncthreads();
    }

#pragma unroll
    for (int i = 0; i < 2; i++) {
        const int r0 = m0 + wm * 32 + 16 * i + g;
        const int r1 = r0 + 8;
#pragma unroll
        for (int j = 0; j < 4; j++) {
            const int c = n0 + wn * 32 + 8 * j + 2 * tig;
            float v00 = acc[i][j][0] + bias[c];
            float v01 = acc[i][j][1] + bias[c + 1];
            float v10 = acc[i][j][2] + bias[c];
            float v11 = acc[i][j][3] + bias[c + 1];
            if (SCALE) { v00 *= QSCALE; v01 *= QSCALE; v10 *= QSCALE; v11 *= QSCALE; }

            if (MODE == 1) {
                Of[(size_t)r0 * EMB + c] = v00;
                Of[(size_t)r0 * EMB + c + 1] = v01;
                Of[(size_t)r1 * EMB + c] = v10;
                Of[(size_t)r1 * EMB + c + 1] = v11;
            } else {
                const int head = blockIdx.x;
                const int d = c & 63;
                const int b0_ = r0 >> 11, q0_ = r0 & 2047;
                const int b1_ = r1 >> 11, q1_ = r1 & 2047;
                if (!TRANSV) {
                    uint h, l;
                    size_t i0 = (((size_t)b0_ * NH + head) * SEQ + q0_) * DH + d;
                    split_pair(v00, v01, h, l);
                    *(uint*)(Oh + i0) = h; *(uint*)(Ol + i0) = l;
                    size_t i1 = (((size_t)b1_ * NH + head) * SEQ + q1_) * DH + d;
                    split_pair(v10, v11, h, l);
                    *(uint*)(Oh + i1) = h; *(uint*)(Ol + i1) = l;
                } else {
                    size_t base0 = (((size_t)b0_ * NH + head) * DH + d) * SEQ;
                    size_t base1 = (((size_t)b1_ * NH + head) * DH + d) * SEQ;
                    __nv_bfloat16 h, l;
                    split_scalar(v00, h, l); Oh[base0 + q0_] = h; Ol[base0 + q0_] = l;
                    split_scalar(v01, h, l); Oh[base0 + SEQ + q0_] = h; Ol[base0 + SEQ + q0_] = l;
                    split_scalar(v10, h, l); Oh[base1 + q1_] = h; Ol[base1 + q1_] = l;
                    split_scalar(v11, h, l); Oh[base1 + SEQ + q1_] = h; Ol[base1 + SEQ + q1_] = l;
                }
            }
        }
    }
}

// ---------------------------------------------------------------------------
// Flash attention: Q frags in registers, cp.async double-buffered K/V,
// ldmatrix fragment loads, exp2-domain softmax (no running max).
// Block = 128 q rows of one (b,h), 8 warps x 16 rows.
// ---------------------------------------------------------------------------
#define ST 72                    // smem row stride (bf16), LDSM conflict-free
#define PL (64 * ST)             // one plane (64 rows)
#define BUFSZ (4 * PL)           // Kh,Kl,Vh,Vl

__global__ void __launch_bounds__(256) attn_mma(
    const __nv_bfloat16* __restrict__ Qh, const __nv_bfloat16* __restrict__ Ql,
    const __nv_bfloat16* __restrict__ Kh, const __nv_bfloat16* __restrict__ Kl,
    const __nv_bfloat16* __restrict__ Vth, const __nv_bfloat16* __restrict__ Vtl,
    __nv_bfloat16* __restrict__ Ch, __nv_bfloat16* __restrict__ Cl)
{
    extern __shared__ __nv_bfloat16 sm[];   // 2 * BUFSZ

    const int bh = blockIdx.y;
    const int q0 = blockIdx.x * 128;
    const int tid = threadIdx.x;
    const int lane = tid & 31, wid = tid >> 5;
    const int g = lane >> 2, tig = lane & 3;

    const size_t qkbase = (size_t)bh * SEQ * DH;
    const uint sm_u32 = (uint)__cvta_generic_to_shared(sm);

    // ldmatrix lane-static offsets (bytes):
    // lanes 0-7: hi plane, cols cb ; 8-15: hi, cols cb+8 ; 16-31: lo plane same
    const uint fr_stat = (uint)((lane & 7) * (ST * 2))
                       + (uint)(((lane >> 3) & 1) * 16)
                       + (uint)((lane >> 4) * (PL * 2));
    const uint k_stat = sm_u32 + fr_stat;              // K planes at 0, PL
    const uint v_stat = sm_u32 + fr_stat + 2 * PL * 2; // V planes at 2PL, 3PL

    // ---- per-thread cp.async source / dest (plane p, row r) ----
    const int p = tid >> 6, r = tid & 63;
    const __nv_bfloat16* gsrc;
    int gadv;
    if (p == 0)      { gsrc = Kh  + qkbase + (size_t)r * DH;     gadv = 64 * DH; }
    else if (p == 1) { gsrc = Kl  + qkbase + (size_t)r * DH;     gadv = 64 * DH; }
    else if (p == 2) { gsrc = Vth + ((size_t)bh * DH + r) * SEQ; gadv = 64; }
    else             { gsrc = Vtl + ((size_t)bh * DH + r) * SEQ; gadv = 64; }
    const uint sdst0 = sm_u32 + (uint)(((size_t)p * PL + r * ST) * 2);

    // ---- prefetch tiles 0 and 1 ----
#pragma unroll
    for (int c = 0; c < 8; c++) cp_async16(sdst0 + c * 16, gsrc + c * 8);
    CP_COMMIT();
#pragma unroll
    for (int c = 0; c < 8; c++)
        cp_async16(sdst0 + BUFSZ * 2 + c * 16, gsrc + gadv + c * 8);
    CP_COMMIT();

    // ---- hoist Q fragments (hi & lo) into registers ----
    uint qfh[4][4], qfl[4][4];
    {
        const int row = q0 + wid * 16 + g;
        const __nv_bfloat16* q0p = Qh + qkbase + (size_t)row * DH;
        const __nv_bfloat16* q1p = q0p + 8 * DH;
        const __nv_bfloat16* l0p = Ql + qkbase + (size_t)row * DH;
        const __nv_bfloat16* l1p = l0p + 8 * DH;
#pragma unroll
        for (int kk = 0; kk < 4; kk++) {
            const int c = kk * 16 + 2 * tig;
            qfh[kk][0] = ldsw(q0p + c);     qfh[kk][1] = ldsw(q1p + c);
            qfh[kk][2] = ldsw(q0p + c + 8); qfh[kk][3] = ldsw(q1p + c + 8);
            qfl[kk][0] = ldsw(l0p + c);     qfl[kk][1] = ldsw(l1p + c);
            qfl[kk][2] = ldsw(l0p + c + 8); qfl[kk][3] = ldsw(l1p + c + 8);
        }
    }

    float l0 = 0.f, l1 = 0.f;
    float o[8][4] = {};

    for (int t = 0; t < 32; t++) {
        const uint bufoff = (uint)((t & 1) * (BUFSZ * 2));

        CP_WAIT1();
        __syncthreads();

        // ---- S = Q K^T ----
        float s[8][4] = {};
#pragma unroll
        for (int kk = 0; kk < 4; kk++) {
            const uint kb = k_stat + bufoff + (uint)(kk * 32);
#pragma unroll
            for (int j = 0; j < 8; j++) {
                uint bh0, bh1, bl0, bl1;
                LDSM4(bh0, bh1, bl0, bl1, kb + (uint)(j * (16 * ST)));
                MMA_BF16(s[j], qfh[kk][0], qfh[kk][1], qfh[kk][2], qfh[kk][3], bh0, bh1);
                MMA_BF16(s[j], qfh[kk][0], qfh[kk][1], qfh[kk][2], qfh[kk][3], bl0, bl1);
                MMA_BF16(s[j], qfl[kk][0], qfl[kk][1], qfl[kk][2], qfl[kk][3], bh0, bh1);
            }
        }

        // ---- softmax (exp2 domain, no max-sub) + P@V ----
#pragma unroll
        for (int kk = 0; kk < 4; kk++) {
            const int j0 = 2 * kk, j1 = 2 * kk + 1;
            float p00 = fast_ex2(s[j0][0]), p01 = fast_ex2(s[j0][1]);
            float p02 = fast_ex2(s[j0][2]), p03 = fast_ex2(s[j0][3]);
            float p10 = fast_ex2(s[j1][0]), p11 = fast_ex2(s[j1][1]);
            float p12 = fast_ex2(s[j1][2]), p13 = fast_ex2(s[j1][3]);
            l0 += p00 + p01 + p10 + p11;
            l1 += p02 + p03 + p12 + p13;
            uint a0, a1, a2, a3, e0, e1, e2, e3;
            split_pair(p00, p01, a0, e0);
            split_pair(p02, p03, a1, e1);
            split_pair(p10, p11, a2, e2);
            split_pair(p12, p13, a3, e3);
            const uint vb = v_stat + bufoff + (uint)(kk * 32);
#pragma unroll
            for (int j = 0; j < 8; j++) {
                uint bh0, bh1, bl0, bl1;
                LDSM4(bh0, bh1, bl0, bl1, vb + (uint)(j * (16 * ST)));
                MMA_BF16(o[j], a0, a1, a2, a3, bh0, bh1);
                MMA_BF16(o[j], a0, a1, a2, a3, bl0, bl1);
                MMA_BF16(o[j], e0, e1, e2, e3, bh0, bh1);
            }
        }

        __syncthreads();

        // ---- prefetch tile t+2 into the buffer just freed ----
        if (t + 2 < 32) {
            const uint sd = sdst0 + (uint)((t & 1) ? BUFSZ * 2 : 0);
            const __nv_bfloat16* gs = gsrc + (size_t)(t + 2) * gadv;
#pragma unroll
            for (int c = 0; c < 8; c++) cp_async16(sd + c * 16, gs + c * 8);
        }
        CP_COMMIT();
    }

    // reduce l across the 4 lanes sharing a row
    l0 += __shfl_xor_sync(0xffffffffu, l0, 1);
    l0 += __shfl_xor_sync(0xffffffffu, l0, 2);
    l1 += __shfl_xor_sync(0xffffffffu, l1, 1);
    l1 += __shfl_xor_sync(0xffffffffu, l1, 2);
    const float inv0 = 1.0f / l0, inv1 = 1.0f / l1;

    // write ctx [b][q][h*64+d] as bf16 hi/lo
    const int b = bh >> 4, h = bh & 15;
    const int row0 = q0 + wid * 16 + g;
    const size_t m0g = (size_t)b * SEQ + row0;
    const size_t m1g = m0g + 8;
#pragma unroll
    for (int j = 0; j < 8; j++) {
        const int col = h * 64 + 8 * j + 2 * tig;
        uint hh, ll;
        split_pair(o[j][0] * inv0, o[j][1] * inv0, hh, ll);
        *(uint*)(Ch + m0g * EMB + col) = hh;
        *(uint*)(Cl + m0g * EMB + col) = ll;
        split_pair(o[j][2] * inv1, o[j][3] * inv1, hh, ll);
        *(uint*)(Ch + m1g * EMB + col) = hh;
        *(uint*)(Cl + m1g * EMB + col) = ll;
    }
}

// ---------------------------------------------------------------------------
extern "C" void kernel_launch(void* const* d_in, const int* in_sizes, int n_in,
                              void* d_out, int out_size)
{
    const float* dec = (const float*)d_in[0];
    const float* enc = (const float*)d_in[1];
    const float* wq  = (const float*)d_in[2];
    const float* bq  = (const float*)d_in[3];
    const float* wk  = (const float*)d_in[4];
    const float* bk  = (const float*)d_in[5];
    const float* wv  = (const float*)d_in[6];
    const float* bv  = (const float*)d_in[7];
    const float* wo  = (const float*)d_in[8];
    const float* bo  = (const float*)d_in[9];
    float* out = (float*)d_out;

    __nv_bfloat16 *dech, *decl, *ench, *encl;
    __nv_bfloat16 *wqh, *wql, *wkh, *wkl, *wvh, *wvl, *woh, *wol;
    __nv_bfloat16 *qh, *ql, *kh, *kl, *vth, *vtl, *ctxh, *ctxl;
    cudaGetSymbolAddress((void**)&dech, g_dech); cudaGetSymbolAddress((void**)&decl, g_decl);
    cudaGetSymbolAddress((void**)&ench, g_ench); cudaGetSymbolAddress((void**)&encl, g_encl);
    cudaGetSymbolAddress((void**)&wqh, g_wqh);   cudaGetSymbolAddress((void**)&wql, g_wql);
    cudaGetSymbolAddress((void**)&wkh, g_wkh);   cudaGetSymbolAddress((void**)&wkl, g_wkl);
    cudaGetSymbolAddress((void**)&wvh, g_wvh);   cudaGetSymbolAddress((void**)&wvl, g_wvl);
    cudaGetSymbolAddress((void**)&woh, g_woh);   cudaGetSymbolAddress((void**)&wol, g_wol);
    cudaGetSymbolAddress((void**)&qh, g_Qh);     cudaGetSymbolAddress((void**)&ql, g_Ql);
    cudaGetSymbolAddress((void**)&kh, g_Kh);     cudaGetSymbolAddress((void**)&kl, g_Kl);
    cudaGetSymbolAddress((void**)&vth, g_Vth);   cudaGetSymbolAddress((void**)&vtl, g_Vtl);
    cudaGetSymbolAddress((void**)&ctxh, g_ctxh); cudaGetSymbolAddress((void**)&ctxl, g_ctxl);

    const int smem_attn = 2 * BUFSZ * (int)sizeof(__nv_bfloat16);  // 73728 B
    cudaFuncSetAttribute(attn_mma, cudaFuncAttributeMaxDynamicSharedMemorySize, smem_attn);

    // 1) split fp32 -> bf16 hi/lo (2 fused launches)
    const int nAct = MTOT * EMB;            // 4,194,304
    const int nW   = EMB * EMB;             // 1,048,576 (all four weight tensors)
    dim3 gduo(nAct / 512, 2);
    split_duo<<<gduo, 256>>>(dec, dech, decl, enc, ench, encl, nAct);
    dim3 gquad(nW / 512, 4);
    split_quad<<<gquad, 256>>>(wq, wqh, wql, wk, wkh, wkl,
                               wv, wvh, wvl, wo, woh, wol, nW);

    // 2) projections
    dim3 gproj(EMB / 64, MTOT / 128);
    gemm_mma<0, true,  false><<<gproj, 256>>>(dech, decl, wqh, wql, bq, qh, ql, nullptr);
    gemm_mma<0, false, false><<<gproj, 256>>>(ench, encl, wkh, wkl, bk, kh, kl, nullptr);
    gemm_mma<0, false, true ><<<gproj, 256>>>(ench, encl, wvh, wvl, bv, vth, vtl, nullptr);

    // 3) attention (6th launch -> captured by ncu -s 5 -c 1)
    dim3 gattn(SEQ / 128, BB * NH);
    attn_mma<<<gattn, 256, smem_attn>>>(qh, ql, kh, kl, vth, vtl, ctxh, ctxl);

    // 4) output projection (fp32 out)
    gemm_mma<1, false, false><<<gproj, 256>>>(ctxh, ctxl, woh, wol, bo, nullptr, nullptr, out);
}

// round 5
// speedup vs baseline: 1.7150x; 1.7150x over previous
#include <cuda_runtime.h>
#include <cuda_bf16.h>
#include <math.h>

typedef unsigned int uint;
typedef __nv_bfloat16 bf;

#define BB 2
#define SEQ 2048
#define EMB 1024
#define NH 16
#define DH 64
#define MTOT (BB * SEQ)          // 4096

// 0.125 * log2(e): fold softmax scale + exp->exp2 conversion into Q
#define QSCALE 0.18033688011112042f

// ---------------- bf16 hi/lo scratch planes ----------------
__device__ bf g_dech[MTOT * EMB], g_decl[MTOT * EMB];
__device__ bf g_ench[MTOT * EMB], g_encl[MTOT * EMB];
__device__ bf g_wqh[NH * EMB * DH], g_wql[NH * EMB * DH];
__device__ bf g_wkh[NH * EMB * DH], g_wkl[NH * EMB * DH];
__device__ bf g_wvh[NH * EMB * DH], g_wvl[NH * EMB * DH];
__device__ bf g_woh[EMB * EMB],    g_wol[EMB * EMB];
__device__ bf g_Qh[BB * NH * SEQ * DH], g_Ql[BB * NH * SEQ * DH];
__device__ bf g_Kh[BB * NH * SEQ * DH], g_Kl[BB * NH * SEQ * DH];
__device__ bf g_Vth[BB * NH * DH * SEQ], g_Vtl[BB * NH * DH * SEQ]; // [bh][d][key]
__device__ bf g_ctxh[MTOT * EMB], g_ctxl[MTOT * EMB];

// ---------------- helpers ----------------
__device__ __forceinline__ uint pack_bf16x2(float lo_elem, float hi_elem) {
    uint r;
    asm("cvt.rn.bf16x2.f32 %0, %1, %2;" : "=r"(r) : "f"(hi_elem), "f"(lo_elem));
    return r;
}
__device__ __forceinline__ void split_pair(float x0, float x1, uint& h, uint& l) {
    h = pack_bf16x2(x0, x1);
    float h0 = __uint_as_float(h << 16);
    float h1 = __uint_as_float(h & 0xffff0000u);
    l = pack_bf16x2(x0 - h0, x1 - h1);
}
__device__ __forceinline__ void split_scalar(float x, bf& h, bf& l) {
    h = __float2bfloat16_rn(x);
    l = __float2bfloat16_rn(x - __bfloat162float(h));
}
__device__ __forceinline__ float fast_ex2(float x) {
    float y; asm("ex2.approx.f32 %0, %1;" : "=f"(y) : "f"(x)); return y;
}

#define MMA_BF16(d, a0, a1, a2, a3, b0, b1)                                    \
    asm volatile(                                                              \
        "mma.sync.aligned.m16n8k16.row.col.f32.bf16.bf16.f32 "                 \
        "{%0,%1,%2,%3}, {%4,%5,%6,%7}, {%8,%9}, {%0,%1,%2,%3};"                \
        : "+f"(d[0]), "+f"(d[1]), "+f"(d[2]), "+f"(d[3])                       \
        : "r"(a0), "r"(a1), "r"(a2), "r"(a3), "r"(b0), "r"(b1))

#define LDSM4(r0, r1, r2, r3, addr)                                            \
    asm volatile("ldmatrix.sync.aligned.m8n8.x4.shared.b16 {%0,%1,%2,%3}, [%4];" \
        : "=r"(r0), "=r"(r1), "=r"(r2), "=r"(r3) : "r"(addr))

#define LDSM4T(r0, r1, r2, r3, addr)                                           \
    asm volatile("ldmatrix.sync.aligned.m8n8.x4.trans.shared.b16 {%0,%1,%2,%3}, [%4];" \
        : "=r"(r0), "=r"(r1), "=r"(r2), "=r"(r3) : "r"(addr))

__device__ __forceinline__ uint ldsw(const bf* p) { return *(const uint*)p; }

__device__ __forceinline__ void cp_async16(uint saddr, const void* gptr) {
    asm volatile("cp.async.cg.shared.global [%0], [%1], 16;" :: "r"(saddr), "l"(gptr));
}
#define CP_COMMIT() asm volatile("cp.async.commit_group;")
#define CP_WAIT1()  asm volatile("cp.async.wait_group 1;")

// ---------------- fused split kernels: fp32 -> bf16 hi/lo ----------------
__device__ __forceinline__ void split_body(const float* __restrict__ x,
    bf* __restrict__ h, bf* __restrict__ l, int n)
{
    int i = (blockIdx.x * 256 + threadIdx.x) * 2;
    if (i < n) {
        float2 v = *(const float2*)(x + i);
        uint hh, ll;
        split_pair(v.x, v.y, hh, ll);
        *(uint*)(h + i) = hh;
        *(uint*)(l + i) = ll;
    }
}

__global__ void __launch_bounds__(256) split_duo(
    const float* __restrict__ x0, bf* h0, bf* l0,
    const float* __restrict__ x1, bf* h1, bf* l1, int n)
{
    if (blockIdx.y == 0) split_body(x0, h0, l0, n);
    else                 split_body(x1, h1, l1, n);
}

__global__ void __launch_bounds__(256) split_quad(
    const float* __restrict__ x0, bf* h0, bf* l0,
    const float* __restrict__ x1, bf* h1, bf* l1,
    const float* __restrict__ x2, bf* h2, bf* l2,
    const float* __restrict__ x3, bf* h3, bf* l3, int n)
{
    switch (blockIdx.y) {
        case 0: split_body(x0, h0, l0, n); break;
        case 1: split_body(x1, h1, l1, n); break;
        case 2: split_body(x2, h2, l2, n); break;
        default: split_body(x3, h3, l3, n); break;
    }
}

// ---------------------------------------------------------------------------
// Pipelined split-3 GEMM core. Tiles: BM=128, BN=64, BK=32.
// A staged [m][k] (stride SA), W staged [k][n] (stride SB, LDSM.trans for B).
// 2-stage cp.async ring. 8 warps (4m x 2n), per-warp 32m x 32n.
// ---------------------------------------------------------------------------
#define SA 40
#define SB 72
#define APL (128 * SA)           // 5120 elems per A plane
#define WPL (32 * SB)            // 2304 elems per W plane
#define STG (2 * APL + 2 * WPL)  // 14848 elems per stage
#define GSMEM (2 * STG * 2)      // bytes (59392)

struct GemmCtx {
    const bf *asrc[4];           // per-thread A cp.async sources (k0=0)
    uint adst[4];                // smem byte offsets (stage 0)
    const bf *wsrc[2];
    uint wdst[2];
    int wadv;                    // W element advance per k-iter
    uint a_stat, b_stat;         // ldmatrix lane-static base addrs
};

__device__ __forceinline__ void gemm_mainloop(GemmCtx& cx, float acc[2][4][4],
                                              int wm, int wn)
{
#pragma unroll 1
    for (int it = 0; it < 32; it++) {
        if (it + 1 < 32) {
            const uint so = (uint)(((it + 1) & 1) * (STG * 2));
            const int ka = (it + 1) * 32;
#pragma unroll
            for (int i = 0; i < 4; i++)
                cp_async16(cx.adst[i] + so, cx.asrc[i] + ka);
#pragma unroll
            for (int i = 0; i < 2; i++)
                cp_async16(cx.wdst[i] + so, cx.wsrc[i] + (it + 1) * cx.wadv);
        }
        CP_COMMIT();
        CP_WAIT1();
        __syncthreads();

        const uint so = (uint)((it & 1) * (STG * 2));
#pragma unroll
        for (int ks = 0; ks < 2; ks++) {
            uint ah[2][4], al2[2][4];
#pragma unroll
            for (int i = 0; i < 2; i++) {
                const uint ab = cx.a_stat + so
                              + (uint)((wm * 32 + 16 * i) * SA * 2 + ks * 32);
                LDSM4(ah[i][0], ah[i][1], ah[i][2], ah[i][3], ab);
                LDSM4(al2[i][0], al2[i][1], al2[i][2], al2[i][3], ab + APL * 2);
            }
#pragma unroll
            for (int j = 0; j < 4; j++) {
                uint bh0, bh1, bl0, bl1;
                LDSM4T(bh0, bh1, bl0, bl1,
                       cx.b_stat + so + (uint)(ks * 16 * SB * 2 + (wn * 32 + 8 * j) * 2));
#pragma unroll
                for (int i = 0; i < 2; i++) {
                    MMA_BF16(acc[i][j], ah[i][0], ah[i][1], ah[i][2], ah[i][3], bh0, bh1);
                    MMA_BF16(acc[i][j], ah[i][0], ah[i][1], ah[i][2], ah[i][3], bl0, bl1);
                    MMA_BF16(acc[i][j], al2[i][0], al2[i][1], al2[i][2], al2[i][3], bh0, bh1);
                }
            }
        }
        __syncthreads();
    }
}

__device__ __forceinline__ void gemm_setup(GemmCtx& cx, uint sm_u32, int tid, int lane,
    const bf* Ah, const bf* Al, int m0,
    const bf* Wh, const bf* Wl, size_t wbase, int ldw, int noff)
{
    // A: 4 chunks of 16B per thread per iter
#pragma unroll
    for (int i = 0; i < 4; i++) {
        int c = i * 256 + tid;
        int quad = c & 3, row = (c >> 2) & 127, plane = (c >> 9) & 1;
        cx.asrc[i] = (plane ? Al : Ah) + (size_t)(m0 + row) * EMB + quad * 8;
        cx.adst[i] = sm_u32 + (uint)((plane * APL + row * SA + quad * 8) * 2);
    }
    // W: 2 chunks per thread per iter; staged [k][n]
#pragma unroll
    for (int i = 0; i < 2; i++) {
        int c = i * 256 + tid;
        int chunk = c & 7, krow = (c >> 3) & 31, plane = (c >> 8) & 1;
        cx.wsrc[i] = (plane ? Wl : Wh) + (wbase + krow) * (size_t)ldw + noff + chunk * 8;
        cx.wdst[i] = sm_u32 + (uint)((2 * APL + plane * WPL + krow * SB + chunk * 8) * 2);
    }
    cx.wadv = 32 * ldw;
    // lane-static ldmatrix addresses
    const uint rowpart = (uint)(((lane & 7) + 8 * ((lane >> 3) & 1)));
    cx.a_stat = sm_u32 + rowpart * (SA * 2) + (uint)((lane >> 4) * 16);
    cx.b_stat = sm_u32 + (uint)(2 * APL * 2) + rowpart * (SB * 2)
              + (uint)((lane >> 4) * (WPL * 2));
    // prologue: stage 0
#pragma unroll
    for (int i = 0; i < 4; i++) cp_async16(cx.adst[i], cx.asrc[i]);
#pragma unroll
    for (int i = 0; i < 2; i++) cp_async16(cx.wdst[i], cx.wsrc[i]);
    CP_COMMIT();
}

// ---- fused QKV projection: grid (16 heads, 32 m-blocks, 3) ----
__global__ void __launch_bounds__(256) qkv_gemm(
    const bf* __restrict__ dech, const bf* __restrict__ decl,
    const bf* __restrict__ ench, const bf* __restrict__ encl,
    const bf* __restrict__ wqh, const bf* __restrict__ wql,
    const bf* __restrict__ wkh, const bf* __restrict__ wkl,
    const bf* __restrict__ wvh, const bf* __restrict__ wvl,
    const float* __restrict__ bq, const float* __restrict__ bk,
    const float* __restrict__ bv,
    bf* __restrict__ Qh, bf* __restrict__ Ql,
    bf* __restrict__ Kh, bf* __restrict__ Kl,
    bf* __restrict__ Vth, bf* __restrict__ Vtl)
{
    extern __shared__ bf smg[];
    const int z = blockIdx.z;
    const int head = blockIdx.x;
    const int m0 = blockIdx.y * 128;
    const int tid = threadIdx.x;
    const int lane = tid & 31, wid = tid >> 5;
    const int wm = wid & 3, wn = wid >> 2;
    const int g = lane >> 2, tig = lane & 3;

    const bf *Ah, *Al, *Wh, *Wl;
    const float* bias;
    if (z == 0)      { Ah = dech; Al = decl; Wh = wqh; Wl = wql; bias = bq; }
    else if (z == 1) { Ah = ench; Al = encl; Wh = wkh; Wl = wkl; bias = bk; }
    else             { Ah = ench; Al = encl; Wh = wvh; Wl = wvl; bias = bv; }

    GemmCtx cx;
    gemm_setup(cx, (uint)__cvta_generic_to_shared(smg), tid, lane,
               Ah, Al, m0, Wh, Wl, (size_t)head * EMB, DH, 0);

    float acc[2][4][4] = {};
    gemm_mainloop(cx, acc, wm, wn);

    // ----- epilogue -----
#pragma unroll
    for (int i = 0; i < 2; i++) {
        const int r0 = m0 + wm * 32 + 16 * i + g;
        const int r1 = r0 + 8;
#pragma unroll
        for (int j = 0; j < 4; j++) {
            const int d = wn * 32 + 8 * j + 2 * tig;   // 0..63 within head
            float v00 = acc[i][j][0] + bias[head * DH + d];
            float v01 = acc[i][j][1] + bias[head * DH + d + 1];
            float v10 = acc[i][j][2] + bias[head * DH + d];
            float v11 = acc[i][j][3] + bias[head * DH + d + 1];
            if (z == 0) { v00 *= QSCALE; v01 *= QSCALE; v10 *= QSCALE; v11 *= QSCALE; }

            const int b0_ = r0 >> 11, q0_ = r0 & 2047;
            const int b1_ = r1 >> 11, q1_ = r1 & 2047;
            if (z < 2) {
                bf *Oh = (z == 0) ? Qh : Kh, *Ol = (z == 0) ? Ql : Kl;
                uint h, l;
                size_t i0 = (((size_t)b0_ * NH + head) * SEQ + q0_) * DH + d;
                split_pair(v00, v01, h, l);
                *(uint*)(Oh + i0) = h; *(uint*)(Ol + i0) = l;
                size_t i1 = (((size_t)b1_ * NH + head) * SEQ + q1_) * DH + d;
                split_pair(v10, v11, h, l);
                *(uint*)(Oh + i1) = h; *(uint*)(Ol + i1) = l;
            } else {
                size_t base0 = (((size_t)b0_ * NH + head) * DH + d) * SEQ;
                size_t base1 = (((size_t)b1_ * NH + head) * DH + d) * SEQ;
                bf h, l;
                split_scalar(v00, h, l); Vth[base0 + q0_] = h; Vtl[base0 + q0_] = l;
                split_scalar(v01, h, l); Vth[base0 + SEQ + q0_] = h; Vtl[base0 + SEQ + q0_] = l;
                split_scalar(v10, h, l); Vth[base1 + q1_] = h; Vtl[base1 + q1_] = l;
                split_scalar(v11, h, l); Vth[base1 + SEQ + q1_] = h; Vtl[base1 + SEQ + q1_] = l;
            }
        }
    }
}

// ---- output projection: grid (16 n-blocks, 32 m-blocks) ----
__global__ void __launch_bounds__(256) wo_gemm(
    const bf* __restrict__ Ah, const bf* __restrict__ Al,
    const bf* __restrict__ Wh, const bf* __restrict__ Wl,
    const float* __restrict__ bias, float* __restrict__ Of)
{
    extern __shared__ bf smg[];
    const int n0 = blockIdx.x * 64;
    const int m0 = blockIdx.y * 128;
    const int tid = threadIdx.x;
    const int lane = tid & 31, wid = tid >> 5;
    const int wm = wid & 3, wn = wid >> 2;
    const int g = lane >> 2, tig = lane & 3;

    GemmCtx cx;
    gemm_setup(cx, (uint)__cvta_generic_to_shared(smg), tid, lane,
               Ah, Al, m0, Wh, Wl, 0, EMB, n0);

    float acc[2][4][4] = {};
    gemm_mainloop(cx, acc, wm, wn);

#pragma unroll
    for (int i = 0; i < 2; i++) {
        const int r0 = m0 + wm * 32 + 16 * i + g;
        const int r1 = r0 + 8;
#pragma unroll
        for (int j = 0; j < 4; j++) {
            const int c = n0 + wn * 32 + 8 * j + 2 * tig;
            Of[(size_t)r0 * EMB + c]     = acc[i][j][0] + bias[c];
            Of[(size_t)r0 * EMB + c + 1] = acc[i][j][1] + bias[c + 1];
            Of[(size_t)r1 * EMB + c]     = acc[i][j][2] + bias[c];
            Of[(size_t)r1 * EMB + c + 1] = acc[i][j][3] + bias[c + 1];
        }
    }
}

// ---------------------------------------------------------------------------
// Flash attention (unchanged from round 4): Q frags in registers, cp.async
// double-buffered K/V, ldmatrix fragment loads, exp2-domain softmax.
// ---------------------------------------------------------------------------
#define ST 72
#define PL (64 * ST)
#define BUFSZ (4 * PL)

__global__ void __launch_bounds__(256) attn_mma(
    const bf* __restrict__ Qh, const bf* __restrict__ Ql,
    const bf* __restrict__ Kh, const bf* __restrict__ Kl,
    const bf* __restrict__ Vth, const bf* __restrict__ Vtl,
    bf* __restrict__ Ch, bf* __restrict__ Cl)
{
    extern __shared__ bf sm[];   // 2 * BUFSZ

    const int bh = blockIdx.y;
    const int q0 = blockIdx.x * 128;
    const int tid = threadIdx.x;
    const int lane = tid & 31, wid = tid >> 5;
    const int g = lane >> 2, tig = lane & 3;

    const size_t qkbase = (size_t)bh * SEQ * DH;
    const uint sm_u32 = (uint)__cvta_generic_to_shared(sm);

    const uint fr_stat = (uint)((lane & 7) * (ST * 2))
                       + (uint)(((lane >> 3) & 1) * 16)
                       + (uint)((lane >> 4) * (PL * 2));
    const uint k_stat = sm_u32 + fr_stat;
    const uint v_stat = sm_u32 + fr_stat + 2 * PL * 2;

    const int p = tid >> 6, r = tid & 63;
    const bf* gsrc;
    int gadv;
    if (p == 0)      { gsrc = Kh  + qkbase + (size_t)r * DH;     gadv = 64 * DH; }
    else if (p == 1) { gsrc = Kl  + qkbase + (size_t)r * DH;     gadv = 64 * DH; }
    else if (p == 2) { gsrc = Vth + ((size_t)bh * DH + r) * SEQ; gadv = 64; }
    else             { gsrc = Vtl + ((size_t)bh * DH + r) * SEQ; gadv = 64; }
    const uint sdst0 = sm_u32 + (uint)(((size_t)p * PL + r * ST) * 2);

#pragma unroll
    for (int c = 0; c < 8; c++) cp_async16(sdst0 + c * 16, gsrc + c * 8);
    CP_COMMIT();
#pragma unroll
    for (int c = 0; c < 8; c++)
        cp_async16(sdst0 + BUFSZ * 2 + c * 16, gsrc + gadv + c * 8);
    CP_COMMIT();

    uint qfh[4][4], qfl[4][4];
    {
        const int row = q0 + wid * 16 + g;
        const bf* q0p = Qh + qkbase + (size_t)row * DH;
        const bf* q1p = q0p + 8 * DH;
        const bf* l0p = Ql + qkbase + (size_t)row * DH;
        const bf* l1p = l0p + 8 * DH;
#pragma unroll
        for (int kk = 0; kk < 4; kk++) {
            const int c = kk * 16 + 2 * tig;
            qfh[kk][0] = ldsw(q0p + c);     qfh[kk][1] = ldsw(q1p + c);
            qfh[kk][2] = ldsw(q0p + c + 8); qfh[kk][3] = ldsw(q1p + c + 8);
            qfl[kk][0] = ldsw(l0p + c);     qfl[kk][1] = ldsw(l1p + c);
            qfl[kk][2] = ldsw(l0p + c + 8); qfl[kk][3] = ldsw(l1p + c + 8);
        }
    }

    float l0 = 0.f, l1 = 0.f;
    float o[8][4] = {};

    for (int t = 0; t < 32; t++) {
        const uint bufoff = (uint)((t & 1) * (BUFSZ * 2));

        CP_WAIT1();
        __syncthreads();

        float s[8][4] = {};
#pragma unroll
        for (int kk = 0; kk < 4; kk++) {
            const uint kb = k_stat + bufoff + (uint)(kk * 32);
#pragma unroll
            for (int j = 0; j < 8; j++) {
                uint bh0, bh1, bl0, bl1;
                LDSM4(bh0, bh1, bl0, bl1, kb + (uint)(j * (16 * ST)));
                MMA_BF16(s[j], qfh[kk][0], qfh[kk][1], qfh[kk][2], qfh[kk][3], bh0, bh1);
                MMA_BF16(s[j], qfh[kk][0], qfh[kk][1], qfh[kk][2], qfh[kk][3], bl0, bl1);
                MMA_BF16(s[j], qfl[kk][0], qfl[kk][1], qfl[kk][2], qfl[kk][3], bh0, bh1);
            }
        }

#pragma unroll
        for (int kk = 0; kk < 4; kk++) {
            const int j0 = 2 * kk, j1 = 2 * kk + 1;
            float p00 = fast_ex2(s[j0][0]), p01 = fast_ex2(s[j0][1]);
            float p02 = fast_ex2(s[j0][2]), p03 = fast_ex2(s[j0][3]);
            float p10 = fast_ex2(s[j1][0]), p11 = fast_ex2(s[j1][1]);
            float p12 = fast_ex2(s[j1][2]), p13 = fast_ex2(s[j1][3]);
            l0 += p00 + p01 + p10 + p11;
            l1 += p02 + p03 + p12 + p13;
            uint a0, a1, a2, a3, e0, e1, e2, e3;
            split_pair(p00, p01, a0, e0);
            split_pair(p02, p03, a1, e1);
            split_pair(p10, p11, a2, e2);
            split_pair(p12, p13, a3, e3);
            const uint vb = v_stat + bufoff + (uint)(kk * 32);
#pragma unroll
            for (int j = 0; j < 8; j++) {
                uint bh0, bh1, bl0, bl1;
                LDSM4(bh0, bh1, bl0, bl1, vb + (uint)(j * (16 * ST)));
                MMA_BF16(o[j], a0, a1, a2, a3, bh0, bh1);
                MMA_BF16(o[j], a0, a1, a2, a3, bl0, bl1);
                MMA_BF16(o[j], e0, e1, e2, e3, bh0, bh1);
            }
        }

        __syncthreads();

        if (t + 2 < 32) {
            const uint sd = sdst0 + (uint)((t & 1) ? BUFSZ * 2 : 0);
            const bf* gs = gsrc + (size_t)(t + 2) * gadv;
#pragma unroll
            for (int c = 0; c < 8; c++) cp_async16(sd + c * 16, gs + c * 8);
        }
        CP_COMMIT();
    }

    l0 += __shfl_xor_sync(0xffffffffu, l0, 1);
    l0 += __shfl_xor_sync(0xffffffffu, l0, 2);
    l1 += __shfl_xor_sync(0xffffffffu, l1, 1);
    l1 += __shfl_xor_sync(0xffffffffu, l1, 2);
    const float inv0 = 1.0f / l0, inv1 = 1.0f / l1;

    const int b = bh >> 4, h = bh & 15;
    const int row0 = q0 + wid * 16 + g;
    const size_t m0g = (size_t)b * SEQ + row0;
    const size_t m1g = m0g + 8;
#pragma unroll
    for (int j = 0; j < 8; j++) {
        const int col = h * 64 + 8 * j + 2 * tig;
        uint hh, ll;
        split_pair(o[j][0] * inv0, o[j][1] * inv0, hh, ll);
        *(uint*)(Ch + m0g * EMB + col) = hh;
        *(uint*)(Cl + m0g * EMB + col) = ll;
        split_pair(o[j][2] * inv1, o[j][3] * inv1, hh, ll);
        *(uint*)(Ch + m1g * EMB + col) = hh;
        *(uint*)(Cl + m1g * EMB + col) = ll;
    }
}

// ---------------------------------------------------------------------------
extern "C" void kernel_launch(void* const* d_in, const int* in_sizes, int n_in,
                              void* d_out, int out_size)
{
    const float* dec = (const float*)d_in[0];
    const float* enc = (const float*)d_in[1];
    const float* wq  = (const float*)d_in[2];
    const float* bq  = (const float*)d_in[3];
    const float* wk  = (const float*)d_in[4];
    const float* bk  = (const float*)d_in[5];
    const float* wv  = (const float*)d_in[6];
    const float* bv  = (const float*)d_in[7];
    const float* wo  = (const float*)d_in[8];
    const float* bo  = (const float*)d_in[9];
    float* out = (float*)d_out;

    bf *dech, *decl, *ench, *encl;
    bf *wqh, *wql, *wkh, *wkl, *wvh, *wvl, *woh, *wol;
    bf *qh, *ql, *kh, *kl, *vth, *vtl, *ctxh, *ctxl;
    cudaGetSymbolAddress((void**)&dech, g_dech); cudaGetSymbolAddress((void**)&decl, g_decl);
    cudaGetSymbolAddress((void**)&ench, g_ench); cudaGetSymbolAddress((void**)&encl, g_encl);
    cudaGetSymbolAddress((void**)&wqh, g_wqh);   cudaGetSymbolAddress((void**)&wql, g_wql);
    cudaGetSymbolAddress((void**)&wkh, g_wkh);   cudaGetSymbolAddress((void**)&wkl, g_wkl);
    cudaGetSymbolAddress((void**)&wvh, g_wvh);   cudaGetSymbolAddress((void**)&wvl, g_wvl);
    cudaGetSymbolAddress((void**)&woh, g_woh);   cudaGetSymbolAddress((void**)&wol, g_wol);
    cudaGetSymbolAddress((void**)&qh, g_Qh);     cudaGetSymbolAddress((void**)&ql, g_Ql);
    cudaGetSymbolAddress((void**)&kh, g_Kh);     cudaGetSymbolAddress((void**)&kl, g_Kl);
    cudaGetSymbolAddress((void**)&vth, g_Vth);   cudaGetSymbolAddress((void**)&vtl, g_Vtl);
    cudaGetSymbolAddress((void**)&ctxh, g_ctxh); cudaGetSymbolAddress((void**)&ctxl, g_ctxl);

    const int smem_attn = 2 * BUFSZ * (int)sizeof(bf);   // 73728 B
    cudaFuncSetAttribute(attn_mma, cudaFuncAttributeMaxDynamicSharedMemorySize, smem_attn);
    cudaFuncSetAttribute(qkv_gemm, cudaFuncAttributeMaxDynamicSharedMemorySize, GSMEM);
    cudaFuncSetAttribute(wo_gemm,  cudaFuncAttributeMaxDynamicSharedMemorySize, GSMEM);

    // 1) split fp32 -> bf16 hi/lo
    const int nAct = MTOT * EMB;
    const int nW   = EMB * EMB;
    dim3 gduo(nAct / 512, 2);
    split_duo<<<gduo, 256>>>(dec, dech, decl, enc, ench, encl, nAct);
    dim3 gquad(nW / 512, 4);
    split_quad<<<gquad, 256>>>(wq, wqh, wql, wk, wkh, wkl,
                               wv, wvh, wvl, wo, woh, wol, nW);

    // 2) fused QKV projections
    dim3 gqkv(NH, MTOT / 128, 3);
    qkv_gemm<<<gqkv, 256, GSMEM>>>(dech, decl, ench, encl,
                                   wqh, wql, wkh, wkl, wvh, wvl,
                                   bq, bk, bv,
                                   qh, ql, kh, kl, vth, vtl);

    // 3) attention
    dim3 gattn(SEQ / 128, BB * NH);
    attn_mma<<<gattn, 256, smem_attn>>>(qh, ql, kh, kl, vth, vtl, ctxh, ctxl);

    // 4) output projection (fp32 out)
    dim3 gwo(EMB / 64, MTOT / 128);
    wo_gemm<<<gwo, 256, GSMEM>>>(ctxh, ctxl, woh, wol, bo, out);
}